// round 9
// baseline (speedup 1.0000x reference)
#include <cuda_runtime.h>
#include <cmath>

// Problem constants
#define BB   64
#define SS   512
#define EE   256
#define HH   512
#define GG   2048
#define NTOT 2560   // GG + HH

// Persistent geometry: 296 blocks = 8 K-slices x 37 col-tiles
#define NB     296
#define NTHR   256
#define KS     8      // K slices of 64
#define NTILE  37     // 30 gate tiles (68/69) + 7 Wd tiles (73/74)
#define WMAX   80     // padded col width (16 tx * 5)

typedef unsigned long long ull;

// packed f32x2 FMA: d = a*b + d (per 32-bit lane)
#define FMA2(d, a, b) asm("fma.rn.f32x2 %0, %1, %2, %0;" : "+l"(d) : "l"(a), "l"(b))

__device__ __forceinline__ void unpack2(ull v, float& lo, float& hi) {
    asm("mov.b64 {%0, %1}, %2;" : "=f"(lo), "=f"(hi) : "l"(v));
}

// ---------------- device scratch ----------------
__device__ float g_uproj[(size_t)BB * SS * GG];          // 256 MB
__device__ float g_h[BB * HH];
__device__ float g_c[BB * HH];
__device__ float g_part[(size_t)KS * BB * NTOT];         // 5.25 MB

__device__ unsigned g_cnt[8 * 32];   // 8 group counters, 128B apart (zero-init)
__device__ unsigned g_root = 0;
__device__ unsigned g_gen  = 0;

// ---------------- hierarchical grid barrier (296 = 8 x 37) ----------------
__device__ __forceinline__ void gsync() {
    __syncthreads();
    if (threadIdx.x == 0) {
        unsigned gen = *(volatile unsigned*)&g_gen;
        __threadfence();
        const unsigned grp = blockIdx.x & 7u;          // 37 blocks per group
        if (atomicAdd(&g_cnt[grp * 32], 1u) == 36u) {
            g_cnt[grp * 32] = 0;
            __threadfence();
            if (atomicAdd(&g_root, 1u) == 7u) {
                g_root = 0;
                __threadfence();
                atomicAdd(&g_gen, 1u);                 // release
            }
        }
        while (*(volatile unsigned*)&g_gen == gen) {}
        __threadfence();
    }
    __syncthreads();
}

// ---------------- u_proj GEMM with FFMA2 (unchanged from R5, passed) ----------------
__global__ __launch_bounds__(256, 2) void uproj_kernel(
    const float* __restrict__ inp, const float* __restrict__ Uw,
    const float* __restrict__ Ub,  const float* __restrict__ Wab)
{
    __shared__ __align__(16) float2 As2[16][132];
    __shared__ __align__(16) float  Bs[16][132];

    const int bm = blockIdx.x, bn = blockIdx.y, tid = threadIdx.x;
    const int tx = tid & 15, ty = tid >> 4;

    ull acc[8][4];
#pragma unroll
    for (int i = 0; i < 8; i++)
#pragma unroll
        for (int j = 0; j < 4; j++) acc[i][j] = 0ull;

    const int m0 = bm * 128, n0 = bn * 128;
    for (int k0 = 0; k0 < EE; k0 += 16) {
#pragma unroll
        for (int i = 0; i < 2; i++) {
            int idx = tid + i * 256;
            int row = idx >> 2, kq = (idx & 3) << 2;
            float4 v = *reinterpret_cast<const float4*>(inp + (size_t)(m0 + row) * EE + k0 + kq);
            As2[kq + 0][row] = make_float2(v.x, v.x);
            As2[kq + 1][row] = make_float2(v.y, v.y);
            As2[kq + 2][row] = make_float2(v.z, v.z);
            As2[kq + 3][row] = make_float2(v.w, v.w);
            float4 w = *reinterpret_cast<const float4*>(Uw + (size_t)(n0 + row) * EE + k0 + kq);
            Bs[kq + 0][row] = w.x; Bs[kq + 1][row] = w.y;
            Bs[kq + 2][row] = w.z; Bs[kq + 3][row] = w.w;
        }
        __syncthreads();
#pragma unroll
        for (int k = 0; k < 16; k++) {
            ulonglong2 A01 = *reinterpret_cast<const ulonglong2*>(&As2[k][ty * 8 + 0]);
            ulonglong2 A23 = *reinterpret_cast<const ulonglong2*>(&As2[k][ty * 8 + 2]);
            ulonglong2 A45 = *reinterpret_cast<const ulonglong2*>(&As2[k][ty * 8 + 4]);
            ulonglong2 A67 = *reinterpret_cast<const ulonglong2*>(&As2[k][ty * 8 + 6]);
            ull av[8] = {A01.x, A01.y, A23.x, A23.y, A45.x, A45.y, A67.x, A67.y};
            ulonglong2 W01 = *reinterpret_cast<const ulonglong2*>(&Bs[k][tx * 8]);
            ulonglong2 W23 = *reinterpret_cast<const ulonglong2*>(&Bs[k][tx * 8 + 4]);
            ull wv[4] = {W01.x, W01.y, W23.x, W23.y};
#pragma unroll
            for (int mi = 0; mi < 8; mi++)
#pragma unroll
                for (int nc = 0; nc < 4; nc++) FMA2(acc[mi][nc], av[mi], wv[nc]);
        }
        __syncthreads();
    }
#pragma unroll
    for (int mi = 0; mi < 8; mi++) {
        int m = m0 + ty * 8 + mi;
        float* dst = g_uproj + (size_t)m * GG + n0 + tx * 8;
#pragma unroll
        for (int nc = 0; nc < 4; nc++) {
            float lo, hi;
            unpack2(acc[mi][nc], lo, hi);
            int g = n0 + tx * 8 + nc * 2;
            dst[nc * 2 + 0] = lo + Ub[g]     + Wab[g];
            dst[nc * 2 + 1] = hi + Ub[g + 1] + Wab[g + 1];
        }
    }
}

// ---------------- persistent weight-stationary scan (256 threads) ----------------
__device__ __forceinline__ float sigmoidf_(float x) { return 1.0f / (1.0f + expf(-x)); }

#define SMEM_WS2 0
#define SMEM_AS  (64 * WMAX * 8)                 // 40960
#define SMEM_TOT (SMEM_AS + 64 * 68 * 4)         // 58368

__global__ __launch_bounds__(NTHR, 2) void scan_kernel(
    const float* __restrict__ ts,
    const float* __restrict__ Wall,
    const float* __restrict__ Wd,
    const float* __restrict__ Wdb,
    float* __restrict__ out)
{
    extern __shared__ __align__(16) char smem[];
    float2 (*Ws2)[WMAX] = reinterpret_cast<float2(*)[WMAX]>(smem + SMEM_WS2);  // (w,w) dup
    float  (*As)[68]    = reinterpret_cast<float(*)[68]>(smem + SMEM_AS);      // [k][b]

    const int tid  = threadIdx.x;
    const int gtid = blockIdx.x * NTHR + tid;
    const int ty = tid >> 4;    // 0..15 : 4 batches (2 pairs)
    const int tx = tid & 15;    // 0..15 : 5 cols

    const int q  = blockIdx.x / NTILE;
    const int ct = blockIdx.x % NTILE;
    const int k0 = q * 64;
    int c0, width, isGate;
    if (ct < 30) { isGate = 1; width = 68 + (ct < 8 ? 1 : 0); c0 = ct * 68 + min(ct, 8); }
    else         { int j = ct - 30; isGate = 0; width = 73 + (j < 1 ? 1 : 0); c0 = 2048 + j * 73 + min(j, 1); }

    // one-time: zero-pad + load duplicated weight tile
    for (int i = tid; i < 64 * WMAX; i += NTHR)
        reinterpret_cast<float2*>(smem)[i] = make_float2(0.f, 0.f);
    __syncthreads();
    for (int lin = tid; lin < width * 16; lin += NTHR) {
        int col = lin >> 4, kq4 = (lin & 15) << 2;
        int row = c0 + col;
        const float* wr = isGate ? (Wall + (size_t)row * HH) : (Wd + (size_t)(row - 2048) * HH);
        float4 v = *reinterpret_cast<const float4*>(wr + k0 + kq4);
        Ws2[kq4 + 0][col] = make_float2(v.x, v.x);
        Ws2[kq4 + 1][col] = make_float2(v.y, v.y);
        Ws2[kq4 + 2][col] = make_float2(v.z, v.z);
        Ws2[kq4 + 3][col] = make_float2(v.w, v.w);
    }

    for (int i = gtid; i < BB * HH; i += NB * NTHR) { g_h[i] = 0.0f; g_c[i] = 0.0f; }
    gsync();

    const float* Asrc = isGate ? g_h : g_c;

    // epilogue warp-chunk assignment: chunk c = blockIdx.x + NB*wid covers pairs [c*32, c*32+32)
    const int wid  = tid >> 5;
    const int lane = tid & 31;

    for (int s = 0; s < SS; s++) {
        // ---- load A slice [64 b x 64 k] -> As[k][b] ----
#pragma unroll
        for (int i = 0; i < 4; i++) {
            int lin = tid + i * NTHR;           // 0..1023
            int b = lin >> 4, kq4 = (lin & 15) << 2;
            float4 v = *reinterpret_cast<const float4*>(Asrc + (size_t)b * HH + k0 + kq4);
            As[kq4 + 0][b] = v.x; As[kq4 + 1][b] = v.y;
            As[kq4 + 2][b] = v.z; As[kq4 + 3][b] = v.w;
        }
        __syncthreads();

        // ---- 64 x 80 x 64 GEMM, packed batch-pairs (2 pairs x 5 cols per thread) ----
        ull acc[2][5];
#pragma unroll
        for (int i = 0; i < 2; i++)
#pragma unroll
            for (int j = 0; j < 5; j++) acc[i][j] = 0ull;

#pragma unroll 8
        for (int k = 0; k < 64; k++) {
            ulonglong2 Aa = *reinterpret_cast<const ulonglong2*>(&As[k][ty * 4]);  // 2 pairs
            ull ap0 = Aa.x, ap1 = Aa.y;
            const ull* wr = reinterpret_cast<const ull*>(&Ws2[k][tx * 5]);
            ull w0 = wr[0], w1 = wr[1], w2 = wr[2], w3 = wr[3], w4 = wr[4];
            FMA2(acc[0][0], ap0, w0); FMA2(acc[0][1], ap0, w1);
            FMA2(acc[0][2], ap0, w2); FMA2(acc[0][3], ap0, w3);
            FMA2(acc[0][4], ap0, w4);
            FMA2(acc[1][0], ap1, w0); FMA2(acc[1][1], ap1, w1);
            FMA2(acc[1][2], ap1, w2); FMA2(acc[1][3], ap1, w3);
            FMA2(acc[1][4], ap1, w4);
        }

        // ---- store deterministic partials ----
        {
            const int rem = width - tx * 5;
            float* pb = g_part + (size_t)q * BB * NTOT + c0 + tx * 5;
#pragma unroll
            for (int p = 0; p < 2; p++) {
                float* d0 = pb + (size_t)(ty * 4 + 2 * p) * NTOT;
                float* d1 = d0 + NTOT;
#pragma unroll
                for (int j = 0; j < 5; j++) {
                    if (j < rem) {
                        float lo, hi;
                        unpack2(acc[p][j], lo, hi);
                        d0[j] = lo;
                        d1[j] = hi;
                    }
                }
            }
        }
        gsync();

        // ---- epilogue: warp-chunks of 32 coalesced pairs, spread over all blocks ----
        {
            const int c = blockIdx.x + NB * wid;     // chunk id; valid if < 512
            if (c < 512) {
                const int p  = c * 32 + lane;        // pair index 0..16383
                const int b  = p >> 8;
                const int j2 = p & 255;

                float2 aF = {0.f,0.f}, aI = {0.f,0.f}, aO = {0.f,0.f}, aC = {0.f,0.f}, aD = {0.f,0.f};
#pragma unroll
                for (int ksl = 0; ksl < KS; ksl++) {
                    const float2* pp = reinterpret_cast<const float2*>(g_part + (size_t)ksl * BB * NTOT + (size_t)b * NTOT);
                    float2 v;
                    v = pp[j2];        aF.x += v.x; aF.y += v.y;
                    v = pp[256 + j2];  aI.x += v.x; aI.y += v.y;
                    v = pp[512 + j2];  aO.x += v.x; aO.y += v.y;
                    v = pp[768 + j2];  aC.x += v.x; aC.y += v.y;
                    v = pp[1024 + j2]; aD.x += v.x; aD.y += v.y;
                }

                const float2* u = reinterpret_cast<const float2*>(g_uproj + ((size_t)b * SS + s) * GG);
                float2 uF = u[j2], uI = u[256 + j2], uO = u[512 + j2], uC = u[768 + j2];
                float2 wb = reinterpret_cast<const float2*>(Wdb)[j2];
                float dec = 1.0f / logf(2.71828182845904523536f + ts[b * SS + s]);
                float2 cold = reinterpret_cast<const float2*>(g_c)[p];

                float cn0, hn0, cn1, hn1;
                {
                    float cs1 = tanhf(aD.x + wb.x);
                    float cadj = (cold.x - cs1) + cs1 * dec;
                    float f  = sigmoidf_(aF.x + uF.x);
                    float i_ = sigmoidf_(aI.x + uI.x);
                    float o  = sigmoidf_(aO.x + uO.x);
                    float ctl = tanhf(aC.x + uC.x);
                    cn0 = f * cadj + i_ * ctl;
                    hn0 = o * tanhf(cn0);
                }
                {
                    float cs1 = tanhf(aD.y + wb.y);
                    float cadj = (cold.y - cs1) + cs1 * dec;
                    float f  = sigmoidf_(aF.y + uF.y);
                    float i_ = sigmoidf_(aI.y + uI.y);
                    float o  = sigmoidf_(aO.y + uO.y);
                    float ctl = tanhf(aC.y + uC.y);
                    cn1 = f * cadj + i_ * ctl;
                    hn1 = o * tanhf(cn1);
                }

                reinterpret_cast<float2*>(g_c)[p] = make_float2(cn0, cn1);
                reinterpret_cast<float2*>(g_h)[p] = make_float2(hn0, hn1);
                reinterpret_cast<float2*>(out)[((size_t)b * SS + s) * (HH / 2) + j2] = make_float2(hn0, hn1);
            }
        }
        gsync();
    }

    for (int i = gtid; i < BB * HH; i += NB * NTHR) {
        out[(size_t)BB * SS * HH + i]           = g_h[i];
        out[(size_t)BB * SS * HH + BB * HH + i] = g_c[i];
    }
}

// ---------------- launch ----------------
extern "C" void kernel_launch(void* const* d_in, const int* in_sizes, int n_in,
                              void* d_out, int out_size) {
    const float* inputs = (const float*)d_in[0];
    const float* tstamp = (const float*)d_in[1];
    const float* Wall_w = (const float*)d_in[2];
    const float* Wall_b = (const float*)d_in[3];
    const float* U_w    = (const float*)d_in[4];
    const float* U_b    = (const float*)d_in[5];
    const float* Wd_w   = (const float*)d_in[6];
    const float* Wd_b   = (const float*)d_in[7];
    float* out = (float*)d_out;

    static int smem_set = 0;
    if (!smem_set) {
        cudaFuncSetAttribute(scan_kernel, cudaFuncAttributeMaxDynamicSharedMemorySize, SMEM_TOT);
        smem_set = 1;
    }

    dim3 gu(BB * SS / 128, GG / 128);
    uproj_kernel<<<gu, 256>>>(inputs, U_w, U_b, Wall_b);

    scan_kernel<<<NB, NTHR, SMEM_TOT>>>(tstamp, Wall_w, Wd_w, Wd_b, out);
}

// round 12
// speedup vs baseline: 1.6922x; 1.6922x over previous
#include <cuda_runtime.h>
#include <cmath>

// Problem constants
#define BB   64
#define SS   512
#define EE   256
#define HH   512
#define GG   2048
#define NTOT 2560   // GG + HH

// Persistent geometry: 296 blocks = 8 K-slices x 37 col-tiles
#define NB     296
#define NTHR   128
#define KS     8      // K slices of 64
#define NTILE  37     // 30 gate tiles (68/69) + 7 Wd tiles (73/74)
#define WMAX   80     // padded col width (16 tx * 5)

typedef unsigned long long ull;

// packed f32x2 FMA: d = a*b + d (per 32-bit lane)
#define FMA2(d, a, b) asm("fma.rn.f32x2 %0, %1, %2, %0;" : "+l"(d) : "l"(a), "l"(b))

__device__ __forceinline__ void unpack2(ull v, float& lo, float& hi) {
    asm("mov.b64 {%0, %1}, %2;" : "=f"(lo), "=f"(hi) : "l"(v));
}

// ---------------- device scratch ----------------
__device__ float g_uproj[(size_t)BB * SS * GG];          // 256 MB
__device__ float g_h[BB * HH];
__device__ float g_c[BB * HH];
__device__ float g_part[(size_t)KS * BB * NTOT];         // 5.25 MB

__device__ unsigned g_cnt[8 * 32];   // 8 group counters, 128B apart (zero-init)
__device__ unsigned g_root = 0;
__device__ unsigned g_gen  = 0;

// ---------------- hierarchical grid barrier (296 = 8 groups x 37) ----------------
__device__ __forceinline__ void gsync() {
    __syncthreads();
    if (threadIdx.x == 0) {
        unsigned gen = *(volatile unsigned*)&g_gen;
        __threadfence();
        const unsigned grp = blockIdx.x & 7u;          // 37 blocks per group
        if (atomicAdd(&g_cnt[grp * 32], 1u) == 36u) {
            g_cnt[grp * 32] = 0;
            __threadfence();
            if (atomicAdd(&g_root, 1u) == 7u) {
                g_root = 0;
                __threadfence();
                atomicAdd(&g_gen, 1u);                 // release
            }
        }
        while (*(volatile unsigned*)&g_gen == gen) {}
        __threadfence();
    }
    __syncthreads();
}

// ---------------- u_proj GEMM with FFMA2 (unchanged, proven) ----------------
__global__ __launch_bounds__(256, 2) void uproj_kernel(
    const float* __restrict__ inp, const float* __restrict__ Uw,
    const float* __restrict__ Ub,  const float* __restrict__ Wab)
{
    __shared__ __align__(16) float2 As2[16][132];
    __shared__ __align__(16) float  Bs[16][132];

    const int bm = blockIdx.x, bn = blockIdx.y, tid = threadIdx.x;
    const int tx = tid & 15, ty = tid >> 4;

    ull acc[8][4];
#pragma unroll
    for (int i = 0; i < 8; i++)
#pragma unroll
        for (int j = 0; j < 4; j++) acc[i][j] = 0ull;

    const int m0 = bm * 128, n0 = bn * 128;
    for (int k0 = 0; k0 < EE; k0 += 16) {
#pragma unroll
        for (int i = 0; i < 2; i++) {
            int idx = tid + i * 256;
            int row = idx >> 2, kq = (idx & 3) << 2;
            float4 v = *reinterpret_cast<const float4*>(inp + (size_t)(m0 + row) * EE + k0 + kq);
            As2[kq + 0][row] = make_float2(v.x, v.x);
            As2[kq + 1][row] = make_float2(v.y, v.y);
            As2[kq + 2][row] = make_float2(v.z, v.z);
            As2[kq + 3][row] = make_float2(v.w, v.w);
            float4 w = *reinterpret_cast<const float4*>(Uw + (size_t)(n0 + row) * EE + k0 + kq);
            Bs[kq + 0][row] = w.x; Bs[kq + 1][row] = w.y;
            Bs[kq + 2][row] = w.z; Bs[kq + 3][row] = w.w;
        }
        __syncthreads();
#pragma unroll
        for (int k = 0; k < 16; k++) {
            ulonglong2 A01 = *reinterpret_cast<const ulonglong2*>(&As2[k][ty * 8 + 0]);
            ulonglong2 A23 = *reinterpret_cast<const ulonglong2*>(&As2[k][ty * 8 + 2]);
            ulonglong2 A45 = *reinterpret_cast<const ulonglong2*>(&As2[k][ty * 8 + 4]);
            ulonglong2 A67 = *reinterpret_cast<const ulonglong2*>(&As2[k][ty * 8 + 6]);
            ull av[8] = {A01.x, A01.y, A23.x, A23.y, A45.x, A45.y, A67.x, A67.y};
            ulonglong2 W01 = *reinterpret_cast<const ulonglong2*>(&Bs[k][tx * 8]);
            ulonglong2 W23 = *reinterpret_cast<const ulonglong2*>(&Bs[k][tx * 8 + 4]);
            ull wv[4] = {W01.x, W01.y, W23.x, W23.y};
#pragma unroll
            for (int mi = 0; mi < 8; mi++)
#pragma unroll
                for (int nc = 0; nc < 4; nc++) FMA2(acc[mi][nc], av[mi], wv[nc]);
        }
        __syncthreads();
    }
#pragma unroll
    for (int mi = 0; mi < 8; mi++) {
        int m = m0 + ty * 8 + mi;
        float* dst = g_uproj + (size_t)m * GG + n0 + tx * 8;
#pragma unroll
        for (int nc = 0; nc < 4; nc++) {
            float lo, hi;
            unpack2(acc[mi][nc], lo, hi);
            int g = n0 + tx * 8 + nc * 2;
            dst[nc * 2 + 0] = lo + Ub[g]     + Wab[g];
            dst[nc * 2 + 1] = hi + Ub[g + 1] + Wab[g + 1];
        }
    }
}

// ---------------- persistent weight-stationary scan (R5 GEMM, 128 threads) ----------------
__device__ __forceinline__ float sigmoidf_(float x) { return 1.0f / (1.0f + expf(-x)); }

#define SMEM_WS2 0
#define SMEM_AS  (64 * WMAX * 8)                 // 40960
#define SMEM_TOT (SMEM_AS + 64 * 68 * 4)         // 58368

__global__ __launch_bounds__(NTHR, 2) void scan_kernel(
    const float* __restrict__ ts,
    const float* __restrict__ Wall,
    const float* __restrict__ Wd,
    const float* __restrict__ Wdb,
    float* __restrict__ out)
{
    extern __shared__ __align__(16) char smem[];
    float2 (*Ws2)[WMAX] = reinterpret_cast<float2(*)[WMAX]>(smem + SMEM_WS2);  // (w,w) dup
    float  (*As)[68]    = reinterpret_cast<float(*)[68]>(smem + SMEM_AS);      // [k][b]

    const int tid  = threadIdx.x;
    const int gtid = blockIdx.x * NTHR + tid;
    const int ty = tid >> 4;    // 0..7  : 4 batch-pairs
    const int tx = tid & 15;    // 0..15 : 5 cols

    const int q  = blockIdx.x / NTILE;
    const int ct = blockIdx.x % NTILE;
    const int k0 = q * 64;
    int c0, width, isGate;
    if (ct < 30) { isGate = 1; width = 68 + (ct < 8 ? 1 : 0); c0 = ct * 68 + min(ct, 8); }
    else         { int j = ct - 30; isGate = 0; width = 73 + (j < 1 ? 1 : 0); c0 = 2048 + j * 73 + min(j, 1); }

    // one-time: zero-pad + load duplicated weight tile
    for (int i = tid; i < 64 * WMAX; i += NTHR)
        reinterpret_cast<float2*>(smem)[i] = make_float2(0.f, 0.f);
    __syncthreads();
    for (int lin = tid; lin < width * 16; lin += NTHR) {
        int col = lin >> 4, kq4 = (lin & 15) << 2;
        int row = c0 + col;
        const float* wr = isGate ? (Wall + (size_t)row * HH) : (Wd + (size_t)(row - 2048) * HH);
        float4 v = *reinterpret_cast<const float4*>(wr + k0 + kq4);
        Ws2[kq4 + 0][col] = make_float2(v.x, v.x);
        Ws2[kq4 + 1][col] = make_float2(v.y, v.y);
        Ws2[kq4 + 2][col] = make_float2(v.z, v.z);
        Ws2[kq4 + 3][col] = make_float2(v.w, v.w);
    }

    for (int i = gtid; i < BB * HH; i += NB * NTHR) { g_h[i] = 0.0f; g_c[i] = 0.0f; }
    gsync();

    const float* Asrc = isGate ? g_h : g_c;

    // epilogue chunk: warp wid of this block handles pairs [cch*32, cch*32+32)
    const int wid  = tid >> 5;
    const int lane = tid & 31;
    const int cch  = blockIdx.x + NB * wid;          // valid if < 512
    const int ep   = cch * 32 + lane;                // pair index
    const int eb   = ep >> 8;
    const int ej2  = ep & 255;

    for (int s = 0; s < SS; s++) {
        // ---- load A slice [64 b x 64 k] -> As[k][b] ----
#pragma unroll
        for (int i = 0; i < 8; i++) {
            int lin = tid + i * NTHR;
            int b = lin >> 4, kq4 = (lin & 15) << 2;
            float4 v = *reinterpret_cast<const float4*>(Asrc + (size_t)b * HH + k0 + kq4);
            As[kq4 + 0][b] = v.x; As[kq4 + 1][b] = v.y;
            As[kq4 + 2][b] = v.z; As[kq4 + 3][b] = v.w;
        }
        __syncthreads();

        // ---- 64 x 80 x 64 GEMM, packed batch-pairs (4 pairs x 5 cols/thread) ----
        ull acc[4][5];
#pragma unroll
        for (int i = 0; i < 4; i++)
#pragma unroll
            for (int j = 0; j < 5; j++) acc[i][j] = 0ull;

#pragma unroll 16
        for (int k = 0; k < 64; k++) {
            ulonglong2 Aa = *reinterpret_cast<const ulonglong2*>(&As[k][ty * 8]);
            ulonglong2 Ab = *reinterpret_cast<const ulonglong2*>(&As[k][ty * 8 + 4]);
            ull ap[4] = {Aa.x, Aa.y, Ab.x, Ab.y};
            const ull* wr = reinterpret_cast<const ull*>(&Ws2[k][tx * 5]);
            ull w0 = wr[0], w1 = wr[1], w2 = wr[2], w3 = wr[3], w4 = wr[4];
#pragma unroll
            for (int p = 0; p < 4; p++) {
                FMA2(acc[p][0], ap[p], w0);
                FMA2(acc[p][1], ap[p], w1);
                FMA2(acc[p][2], ap[p], w2);
                FMA2(acc[p][3], ap[p], w3);
                FMA2(acc[p][4], ap[p], w4);
            }
        }

        // ---- store deterministic partials ----
        {
            const int rem = width - tx * 5;
            float* pb = g_part + (size_t)q * BB * NTOT + c0 + tx * 5;
#pragma unroll
            for (int p = 0; p < 4; p++) {
                float* d0 = pb + (size_t)(ty * 8 + 2 * p) * NTOT;
                float* d1 = d0 + NTOT;
#pragma unroll
                for (int j = 0; j < 5; j++) {
                    if (j < rem) {
                        float lo, hi;
                        unpack2(acc[p][j], lo, hi);
                        d0[j] = lo;
                        d1[j] = hi;
                    }
                }
            }
        }

        // ---- prefetch barrier-independent epilogue operands (overlap gsync) ----
        float2 uF, uI, uO, uC, wb, cold;
        float dec = 0.f;
        if (cch < 512) {
            const float2* u = reinterpret_cast<const float2*>(g_uproj + ((size_t)eb * SS + s) * GG);
            uF = u[ej2]; uI = u[256 + ej2]; uO = u[512 + ej2]; uC = u[768 + ej2];
            wb = reinterpret_cast<const float2*>(Wdb)[ej2];
            dec = 1.0f / logf(2.71828182845904523536f + ts[eb * SS + s]);
            cold = reinterpret_cast<const float2*>(g_c)[ep];
        }
        gsync();

        // ---- epilogue: 512 warp-chunks of 32 coalesced pairs ----
        if (cch < 512) {
            float2 aF = {0.f,0.f}, aI = {0.f,0.f}, aO = {0.f,0.f}, aC = {0.f,0.f}, aD = {0.f,0.f};
#pragma unroll
            for (int ksl = 0; ksl < KS; ksl++) {
                const float2* pp = reinterpret_cast<const float2*>(g_part + (size_t)ksl * BB * NTOT + (size_t)eb * NTOT);
                float2 v;
                v = pp[ej2];        aF.x += v.x; aF.y += v.y;
                v = pp[256 + ej2];  aI.x += v.x; aI.y += v.y;
                v = pp[512 + ej2];  aO.x += v.x; aO.y += v.y;
                v = pp[768 + ej2];  aC.x += v.x; aC.y += v.y;
                v = pp[1024 + ej2]; aD.x += v.x; aD.y += v.y;
            }

            float cn0, hn0, cn1, hn1;
            {
                float cs1 = tanhf(aD.x + wb.x);
                float cadj = (cold.x - cs1) + cs1 * dec;
                float f  = sigmoidf_(aF.x + uF.x);
                float i_ = sigmoidf_(aI.x + uI.x);
                float o  = sigmoidf_(aO.x + uO.x);
                float ctl = tanhf(aC.x + uC.x);
                cn0 = f * cadj + i_ * ctl;
                hn0 = o * tanhf(cn0);
            }
            {
                float cs1 = tanhf(aD.y + wb.y);
                float cadj = (cold.y - cs1) + cs1 * dec;
                float f  = sigmoidf_(aF.y + uF.y);
                float i_ = sigmoidf_(aI.y + uI.y);
                float o  = sigmoidf_(aO.y + uO.y);
                float ctl = tanhf(aC.y + uC.y);
                cn1 = f * cadj + i_ * ctl;
                hn1 = o * tanhf(cn1);
            }

            reinterpret_cast<float2*>(g_c)[ep] = make_float2(cn0, cn1);
            reinterpret_cast<float2*>(g_h)[ep] = make_float2(hn0, hn1);
            reinterpret_cast<float2*>(out)[((size_t)eb * SS + s) * (HH / 2) + ej2] = make_float2(hn0, hn1);
        }
        gsync();
    }

    for (int i = gtid; i < BB * HH; i += NB * NTHR) {
        out[(size_t)BB * SS * HH + i]           = g_h[i];
        out[(size_t)BB * SS * HH + BB * HH + i] = g_c[i];
    }
}

// ---------------- launch ----------------
extern "C" void kernel_launch(void* const* d_in, const int* in_sizes, int n_in,
                              void* d_out, int out_size) {
    const float* inputs = (const float*)d_in[0];
    const float* tstamp = (const float*)d_in[1];
    const float* Wall_w = (const float*)d_in[2];
    const float* Wall_b = (const float*)d_in[3];
    const float* U_w    = (const float*)d_in[4];
    const float* U_b    = (const float*)d_in[5];
    const float* Wd_w   = (const float*)d_in[6];
    const float* Wd_b   = (const float*)d_in[7];
    float* out = (float*)d_out;

    static int smem_set = 0;
    if (!smem_set) {
        cudaFuncSetAttribute(scan_kernel, cudaFuncAttributeMaxDynamicSharedMemorySize, SMEM_TOT);
        smem_set = 1;
    }

    dim3 gu(BB * SS / 128, GG / 128);
    uproj_kernel<<<gu, 256>>>(inputs, U_w, U_b, Wall_b);

    scan_kernel<<<NB, NTHR, SMEM_TOT>>>(tstamp, Wall_w, Wd_w, Wd_b, out);
}